// round 7
// baseline (speedup 1.0000x reference)
#include <cuda_runtime.h>
#include <cuda_bf16.h>
#include <mma.h>
#include <cstdint>
#include <cstddef>

using namespace nvcuda;

#define B_ 4096
#define T_ 80
#define V_ 10000
#define E_ 100
#define U_ 1024

#define KTOT 1152            // 1024 (Wh) + 128 (Wx padded from 100)
#define EPAD 128             // padded embedding width
#define NCHUNK 36            // KTOT / 32
#define MT 256
#define NT 128
#define KC 32
#define NSTAGE 3
#define NTHREADS 512
#define LDAB 40              // leading dim in bf16 elements (80 B, multiple of 16 B)

// byte sizes
#define A_PLANE_B (MT * LDAB * 2)        // 20480
#define A_STAGE_B (2 * A_PLANE_B)        // 40960 (hi + lo)
#define B_PLANE_B (NT * LDAB * 2)        // 10240
#define B_STAGE_B (2 * B_PLANE_B)        // 20480
#define SM_A_OFF   0
#define SM_B_OFF   (NSTAGE * A_STAGE_B)                 // 122880
#define SM_SCR_OFF (SM_B_OFF + NSTAGE * B_STAGE_B)      // 184320
#define SM_IDX_OFF (SM_SCR_OFF + 16 * 16 * 24 * 4)      // 208896
#define SMEM_TOTAL (SM_IDX_OFF + MT * 4)                // 209920

// ---- device scratch (allocation-free) ----
__device__ __align__(256) __nv_bfloat16 g_h_hi[2][(size_t)B_ * U_];
__device__ __align__(256) __nv_bfloat16 g_h_lo[2][(size_t)B_ * U_];
__device__ __align__(256) __nv_bfloat16 g_Bth[(size_t)U_ * KTOT];   // [n][k] hi
__device__ __align__(256) __nv_bfloat16 g_Btl[(size_t)U_ * KTOT];   // [n][k] lo
__device__ __align__(256) __nv_bfloat16 g_emb_hi[(size_t)V_ * EPAD];
__device__ __align__(256) __nv_bfloat16 g_emb_lo[(size_t)V_ * EPAD];

static __device__ __forceinline__ uint32_t smem_u32(const void* p) {
    uint32_t a;
    asm("{ .reg .u64 t; cvta.to.shared.u64 t, %1; cvt.u32.u64 %0, t; }" : "=r"(a) : "l"(p));
    return a;
}
static __device__ __forceinline__ void cp_async16(uint32_t s, const void* g) {
    asm volatile("cp.async.cg.shared.global [%0], [%1], 16;" :: "r"(s), "l"(g));
}
static __device__ __forceinline__ void split_bf16(float v, __nv_bfloat16& hi, __nv_bfloat16& lo) {
    hi = __float2bfloat16(v);
    lo = __float2bfloat16(v - __bfloat162float(hi));
}

// ---------------- prep kernels ----------------
__global__ void prep_bt_kernel(const float* __restrict__ Wh, const float* __restrict__ Wx) {
    int idx = blockIdx.x * 256 + threadIdx.x;
    if (idx >= U_ * KTOT) return;
    int n = idx / KTOT;
    int k = idx - n * KTOT;
    float v = 0.0f;
    if (k < U_)            v = Wh[(size_t)k * U_ + n];
    else if (k < U_ + E_)  v = Wx[(size_t)(k - U_) * U_ + n];
    __nv_bfloat16 hi, lo; split_bf16(v, hi, lo);
    g_Bth[idx] = hi; g_Btl[idx] = lo;
}
__global__ void prep_emb_kernel(const float* __restrict__ emb) {
    int idx = blockIdx.x * 256 + threadIdx.x;
    if (idx >= V_ * EPAD) return;
    int tok = idx >> 7;
    int k = idx & (EPAD - 1);
    float v = (k < E_) ? emb[(size_t)tok * E_ + k] : 0.0f;
    __nv_bfloat16 hi, lo; split_bf16(v, hi, lo);
    g_emb_hi[idx] = hi; g_emb_lo[idx] = lo;
}
__global__ void zero_h_kernel() {
    size_t i = (size_t)blockIdx.x * blockDim.x + threadIdx.x;
    if (i < (size_t)B_ * U_) {
        g_h_hi[0][i] = __float2bfloat16(0.0f);
        g_h_lo[0][i] = __float2bfloat16(0.0f);
    }
}

// ---------------- recurrence step: wmma bf16 m16n16k16, 3-MMA split ----------------
// Grid: (U_/NT = 8, B_/MT = 16), 512 threads (16 warps, 4x4 -> 64x32 warp tiles).
__global__ __launch_bounds__(NTHREADS, 1)
void rnn_step_bf16(const int* __restrict__ inputs, const float* __restrict__ bvec, int t)
{
    extern __shared__ char smem[];
    float* sScr = (float*)(smem + SM_SCR_OFF);
    int*   sIdx = (int*)(smem + SM_IDX_OFF);
    const uint32_t sbase = smem_u32(smem);

    const int tid = threadIdx.x;
    const int wid = tid >> 5;
    const int lane = tid & 31;
    const int warp_m = wid & 3;       // 4 m-tiles of 64
    const int warp_n = wid >> 2;      // 4 n-tiles of 32
    const int n0 = blockIdx.x * NT;
    const int m0 = blockIdx.y * MT;

    const __nv_bfloat16* __restrict__ hh = g_h_hi[t & 1];
    const __nv_bfloat16* __restrict__ hl = g_h_lo[t & 1];
    __nv_bfloat16* __restrict__ nh = g_h_hi[(t & 1) ^ 1];
    __nv_bfloat16* __restrict__ nl = g_h_lo[(t & 1) ^ 1];

    if (tid < MT) sIdx[tid] = inputs[(size_t)(m0 + tid) * T_ + t];
    __syncthreads();

    wmma::fragment<wmma::accumulator, 16, 16, 16, float> acc[4][2];
#pragma unroll
    for (int i = 0; i < 4; i++)
#pragma unroll
        for (int j = 0; j < 2; j++) wmma::fill_fragment(acc[i][j], 0.0f);

    auto issue = [&](int c) {
        const int s = c % NSTAGE;
        const uint32_t aHiB = sbase + SM_A_OFF + (uint32_t)(s * A_STAGE_B);
        const uint32_t aLoB = aHiB + A_PLANE_B;
        if (c < 32) {
            const __nv_bfloat16* sh = hh + (size_t)m0 * U_ + c * KC;
            const __nv_bfloat16* sl = hl + (size_t)m0 * U_ + c * KC;
#pragma unroll
            for (int r = 0; r < 2; r++) {
                int idx = r * NTHREADS + tid;
                int row = idx >> 2, sc = idx & 3;
                uint32_t off = (uint32_t)(row * (LDAB * 2) + sc * 16);
                cp_async16(aHiB + off, sh + (size_t)row * U_ + sc * 8);
                cp_async16(aLoB + off, sl + (size_t)row * U_ + sc * 8);
            }
        } else {
            const int kb = (c - 32) * KC;
#pragma unroll
            for (int r = 0; r < 2; r++) {
                int idx = r * NTHREADS + tid;
                int row = idx >> 2, sc = idx & 3;
                uint32_t off = (uint32_t)(row * (LDAB * 2) + sc * 16);
                size_t g = (size_t)sIdx[row] * EPAD + kb + sc * 8;
                cp_async16(aHiB + off, g_emb_hi + g);
                cp_async16(aLoB + off, g_emb_lo + g);
            }
        }
        const uint32_t bHiB = sbase + SM_B_OFF + (uint32_t)(s * B_STAGE_B);
        const uint32_t bLoB = bHiB + B_PLANE_B;
        const __nv_bfloat16* bh = g_Bth + (size_t)n0 * KTOT + c * KC;
        const __nv_bfloat16* bl = g_Btl + (size_t)n0 * KTOT + c * KC;
        {
            int row = tid >> 2, sc = tid & 3;
            uint32_t off = (uint32_t)(row * (LDAB * 2) + sc * 16);
            cp_async16(bHiB + off, bh + (size_t)row * KTOT + sc * 8);
            cp_async16(bLoB + off, bl + (size_t)row * KTOT + sc * 8);
        }
        asm volatile("cp.async.commit_group;" ::: "memory");
    };

    issue(0); issue(1); issue(2);

    for (int c = 0; c < NCHUNK; c++) {
        if (c <= NCHUNK - 3)      asm volatile("cp.async.wait_group 2;" ::: "memory");
        else if (c == NCHUNK - 2) asm volatile("cp.async.wait_group 1;" ::: "memory");
        else                      asm volatile("cp.async.wait_group 0;" ::: "memory");
        __syncthreads();

        const int s = c % NSTAGE;
        const __nv_bfloat16* AsH =
            (const __nv_bfloat16*)(smem + SM_A_OFF + s * A_STAGE_B) + warp_m * 64 * LDAB;
        const __nv_bfloat16* AsL = AsH + A_PLANE_B / 2;
        const __nv_bfloat16* BsH =
            (const __nv_bfloat16*)(smem + SM_B_OFF + s * B_STAGE_B) + warp_n * 32 * LDAB;
        const __nv_bfloat16* BsL = BsH + B_PLANE_B / 2;

#pragma unroll
        for (int k16 = 0; k16 < 2; k16++) {
            wmma::fragment<wmma::matrix_b, 16, 16, 16, __nv_bfloat16, wmma::col_major> bHf[2], bLf[2];
#pragma unroll
            for (int j = 0; j < 2; j++) {
                wmma::load_matrix_sync(bHf[j], BsH + j * 16 * LDAB + k16 * 16, LDAB);
                wmma::load_matrix_sync(bLf[j], BsL + j * 16 * LDAB + k16 * 16, LDAB);
            }
#pragma unroll
            for (int i = 0; i < 4; i++) {
                wmma::fragment<wmma::matrix_a, 16, 16, 16, __nv_bfloat16, wmma::row_major> aHf, aLf;
                wmma::load_matrix_sync(aHf, AsH + i * 16 * LDAB + k16 * 16, LDAB);
                wmma::load_matrix_sync(aLf, AsL + i * 16 * LDAB + k16 * 16, LDAB);
#pragma unroll
                for (int j = 0; j < 2; j++) {
                    wmma::mma_sync(acc[i][j], aHf, bHf[j], acc[i][j]);
                    wmma::mma_sync(acc[i][j], aLf, bHf[j], acc[i][j]);
                    wmma::mma_sync(acc[i][j], aHf, bLf[j], acc[i][j]);
                }
            }
        }
        __syncthreads();
        if (c + NSTAGE < NCHUNK) issue(c + NSTAGE);
    }

    // ---- epilogue: bias + tanh + bf16 hi/lo split + store ----
    float* scr = sScr + wid * (16 * 24);
    const int er = lane >> 1;
    const int ec = (lane & 1) * 8;
#pragma unroll
    for (int mi = 0; mi < 4; mi++) {
#pragma unroll
        for (int ni = 0; ni < 2; ni++) {
            wmma::store_matrix_sync(scr, acc[mi][ni], 24, wmma::mem_row_major);
            __syncwarp();
            int gr = m0 + warp_m * 64 + mi * 16 + er;
            int gc = n0 + warp_n * 32 + ni * 16 + ec;
            float4 v0 = *(float4*)(scr + er * 24 + ec);
            float4 v1 = *(float4*)(scr + er * 24 + ec + 4);
            const float* bb = bvec + gc;
            float vv[8] = { v0.x + bb[0], v0.y + bb[1], v0.z + bb[2], v0.w + bb[3],
                            v1.x + bb[4], v1.y + bb[5], v1.z + bb[6], v1.w + bb[7] };
            __align__(16) __nv_bfloat162 ph[4];
            __align__(16) __nv_bfloat162 pl[4];
#pragma unroll
            for (int e = 0; e < 4; e++) {
                __nv_bfloat16 h0, l0, h1, l1;
                split_bf16(tanhf(vv[2 * e]), h0, l0);
                split_bf16(tanhf(vv[2 * e + 1]), h1, l1);
                ph[e] = __halves2bfloat162(h0, h1);
                pl[e] = __halves2bfloat162(l0, l1);
            }
            size_t o = (size_t)gr * U_ + gc;
            *(uint4*)(nh + o) = *(uint4*)ph;
            *(uint4*)(nl + o) = *(uint4*)pl;
            __syncwarp();
        }
    }
}

// out[row] = h_last[row, :] @ Wo + bo
__global__ void final_proj_kernel(const float* __restrict__ Wo,
                                  const float* __restrict__ bo,
                                  float* __restrict__ out)
{
    const __nv_bfloat16* hh = g_h_hi[0];   // T_=80 even -> final state in buffer 0
    const __nv_bfloat16* hl = g_h_lo[0];
    int row = blockIdx.x;
    int tid = threadIdx.x;     // 128 threads
    float s = 0.0f;
    size_t base = (size_t)row * U_;
#pragma unroll 4
    for (int i = tid; i < U_; i += 128) {
        float hv = __bfloat162float(hh[base + i]) + __bfloat162float(hl[base + i]);
        s += hv * Wo[i];
    }
#pragma unroll
    for (int o = 16; o > 0; o >>= 1) s += __shfl_down_sync(0xffffffffu, s, o);
    __shared__ float red[4];
    if ((tid & 31) == 0) red[tid >> 5] = s;
    __syncthreads();
    if (tid == 0) out[row] = red[0] + red[1] + red[2] + red[3] + bo[0];
}

extern "C" void kernel_launch(void* const* d_in, const int* in_sizes, int n_in,
                              void* d_out, int out_size)
{
    const int*   inputs = (const int*)  d_in[0];
    const float* emb    = (const float*)d_in[1];
    const float* Wx     = (const float*)d_in[2];
    const float* Wh     = (const float*)d_in[3];
    const float* b      = (const float*)d_in[4];
    const float* Wo     = (const float*)d_in[5];
    const float* bo     = (const float*)d_in[6];
    float* out = (float*)d_out;

    cudaFuncSetAttribute(rnn_step_bf16, cudaFuncAttributeMaxDynamicSharedMemorySize,
                         SMEM_TOTAL);

    // Prep: split/transposed/padded bf16 weights + embedding, h0 = 0
    prep_bt_kernel<<<(U_ * KTOT + 255) / 256, 256>>>(Wh, Wx);
    prep_emb_kernel<<<(V_ * EPAD + 255) / 256, 256>>>(emb);
    {
        size_t n = (size_t)B_ * U_;
        zero_h_kernel<<<(int)((n + 255) / 256), 256>>>();
    }

    // 80 recurrence steps (ping-pong hi/lo planes)
    dim3 grid(U_ / NT, B_ / MT);
    for (int t = 0; t < T_; t++) {
        rnn_step_bf16<<<grid, NTHREADS, SMEM_TOTAL>>>(inputs, b, t);
    }

    final_proj_kernel<<<B_, 128>>>(Wo, bo, out);
}

// round 8
// speedup vs baseline: 1.6702x; 1.6702x over previous
#include <cuda_runtime.h>
#include <cuda_bf16.h>
#include <mma.h>
#include <cstdint>
#include <cstddef>

using namespace nvcuda;

#define B_ 4096
#define T_ 80
#define V_ 10000
#define E_ 100
#define U_ 1024

#define KTOT 1152            // 1024 (Wh) + 128 (Wx padded from 100)
#define EPAD 128             // padded embedding width
#define NCHUNK 36            // KTOT / 32
#define MT 128
#define NT 128
#define KC 32
#define NSTAGE 2
#define NTHREADS 128
#define LDAB 40              // leading dim in bf16 elements (80 B, multiple of 16 B)

// byte sizes
#define A_PLANE_B (MT * LDAB * 2)        // 10240
#define A_STAGE_B (2 * A_PLANE_B)        // 20480 (hi + lo)
#define B_PLANE_B (NT * LDAB * 2)        // 10240
#define B_STAGE_B (2 * B_PLANE_B)        // 20480
#define SM_A_OFF   0
#define SM_B_OFF   (NSTAGE * A_STAGE_B)                 // 40960
#define SM_SCR_OFF (SM_B_OFF + NSTAGE * B_STAGE_B)      // 81920
#define SM_IDX_OFF (SM_SCR_OFF + 4 * 16 * 24 * 4)       // 88064
#define SMEM_TOTAL (SM_IDX_OFF + MT * 4)                // 88576

// ---- device scratch (allocation-free) ----
__device__ __align__(256) __nv_bfloat16 g_h_hi[2][(size_t)B_ * U_];
__device__ __align__(256) __nv_bfloat16 g_h_lo[2][(size_t)B_ * U_];
__device__ __align__(256) __nv_bfloat16 g_Bth[(size_t)U_ * KTOT];   // [n][k] hi
__device__ __align__(256) __nv_bfloat16 g_Btl[(size_t)U_ * KTOT];   // [n][k] lo
__device__ __align__(256) __nv_bfloat16 g_emb_hi[(size_t)V_ * EPAD];
__device__ __align__(256) __nv_bfloat16 g_emb_lo[(size_t)V_ * EPAD];

static __device__ __forceinline__ uint32_t smem_u32(const void* p) {
    uint32_t a;
    asm("{ .reg .u64 t; cvta.to.shared.u64 t, %1; cvt.u32.u64 %0, t; }" : "=r"(a) : "l"(p));
    return a;
}
static __device__ __forceinline__ void cp_async16(uint32_t s, const void* g) {
    asm volatile("cp.async.cg.shared.global [%0], [%1], 16;" :: "r"(s), "l"(g));
}
static __device__ __forceinline__ void split_bf16(float v, __nv_bfloat16& hi, __nv_bfloat16& lo) {
    hi = __float2bfloat16(v);
    lo = __float2bfloat16(v - __bfloat162float(hi));
}

// ---------------- prep kernels ----------------
__global__ void prep_bt_kernel(const float* __restrict__ Wh, const float* __restrict__ Wx) {
    int idx = blockIdx.x * 256 + threadIdx.x;
    if (idx >= U_ * KTOT) return;
    int n = idx / KTOT;
    int k = idx - n * KTOT;
    float v = 0.0f;
    if (k < U_)            v = Wh[(size_t)k * U_ + n];
    else if (k < U_ + E_)  v = Wx[(size_t)(k - U_) * U_ + n];
    __nv_bfloat16 hi, lo; split_bf16(v, hi, lo);
    g_Bth[idx] = hi; g_Btl[idx] = lo;
}
__global__ void prep_emb_kernel(const float* __restrict__ emb) {
    int idx = blockIdx.x * 256 + threadIdx.x;
    if (idx >= V_ * EPAD) return;
    int tok = idx >> 7;
    int k = idx & (EPAD - 1);
    float v = (k < E_) ? emb[(size_t)tok * E_ + k] : 0.0f;
    __nv_bfloat16 hi, lo; split_bf16(v, hi, lo);
    g_emb_hi[idx] = hi; g_emb_lo[idx] = lo;
}
__global__ void zero_h_kernel() {
    size_t i = (size_t)blockIdx.x * blockDim.x + threadIdx.x;
    if (i < (size_t)B_ * U_) {
        g_h_hi[0][i] = __float2bfloat16(0.0f);
        g_h_lo[0][i] = __float2bfloat16(0.0f);
    }
}

// ---------------- recurrence step: wmma bf16 m16n16k16, 3-MMA split ----------------
// Grid: (U_/NT = 8, B_/MT = 32) = 256 CTAs, 128 threads (4 warps, 2x2 -> 64x64 tiles).
// 2 CTAs resident per SM: cross-CTA overlap hides barrier + producer bubbles.
__global__ __launch_bounds__(NTHREADS, 2)
void rnn_step_bf16(const int* __restrict__ inputs, const float* __restrict__ bvec, int t)
{
    extern __shared__ char smem[];
    float* sScr = (float*)(smem + SM_SCR_OFF);
    int*   sIdx = (int*)(smem + SM_IDX_OFF);
    const uint32_t sbase = smem_u32(smem);

    const int tid = threadIdx.x;
    const int wid = tid >> 5;
    const int lane = tid & 31;
    const int warp_m = wid & 1;       // 2 m-tiles of 64
    const int warp_n = wid >> 1;      // 2 n-tiles of 64
    const int n0 = blockIdx.x * NT;
    const int m0 = blockIdx.y * MT;

    const __nv_bfloat16* __restrict__ hh = g_h_hi[t & 1];
    const __nv_bfloat16* __restrict__ hl = g_h_lo[t & 1];
    __nv_bfloat16* __restrict__ nh = g_h_hi[(t & 1) ^ 1];
    __nv_bfloat16* __restrict__ nl = g_h_lo[(t & 1) ^ 1];

    sIdx[tid] = inputs[(size_t)(m0 + tid) * T_ + t];
    __syncthreads();

    wmma::fragment<wmma::accumulator, 16, 16, 16, float> acc[4][4];
#pragma unroll
    for (int i = 0; i < 4; i++)
#pragma unroll
        for (int j = 0; j < 4; j++) wmma::fill_fragment(acc[i][j], 0.0f);

    auto issue = [&](int c) {
        const int s = c % NSTAGE;
        const uint32_t aHiB = sbase + SM_A_OFF + (uint32_t)(s * A_STAGE_B);
        const uint32_t aLoB = aHiB + A_PLANE_B;
        if (c < 32) {
            const __nv_bfloat16* sh = hh + (size_t)m0 * U_ + c * KC;
            const __nv_bfloat16* sl = hl + (size_t)m0 * U_ + c * KC;
#pragma unroll
            for (int r = 0; r < 4; r++) {
                int idx = r * NTHREADS + tid;
                int row = idx >> 2, sc = idx & 3;
                uint32_t off = (uint32_t)(row * (LDAB * 2) + sc * 16);
                cp_async16(aHiB + off, sh + (size_t)row * U_ + sc * 8);
                cp_async16(aLoB + off, sl + (size_t)row * U_ + sc * 8);
            }
        } else {
            const int kb = (c - 32) * KC;
#pragma unroll
            for (int r = 0; r < 4; r++) {
                int idx = r * NTHREADS + tid;
                int row = idx >> 2, sc = idx & 3;
                uint32_t off = (uint32_t)(row * (LDAB * 2) + sc * 16);
                size_t g = (size_t)sIdx[row] * EPAD + kb + sc * 8;
                cp_async16(aHiB + off, g_emb_hi + g);
                cp_async16(aLoB + off, g_emb_lo + g);
            }
        }
        const uint32_t bHiB = sbase + SM_B_OFF + (uint32_t)(s * B_STAGE_B);
        const uint32_t bLoB = bHiB + B_PLANE_B;
        const __nv_bfloat16* bh = g_Bth + (size_t)n0 * KTOT + c * KC;
        const __nv_bfloat16* bl = g_Btl + (size_t)n0 * KTOT + c * KC;
#pragma unroll
        for (int r = 0; r < 4; r++) {
            int idx = r * NTHREADS + tid;
            int row = idx >> 2, sc = idx & 3;
            uint32_t off = (uint32_t)(row * (LDAB * 2) + sc * 16);
            cp_async16(bHiB + off, bh + (size_t)row * KTOT + sc * 8);
            cp_async16(bLoB + off, bl + (size_t)row * KTOT + sc * 8);
        }
        asm volatile("cp.async.commit_group;" ::: "memory");
    };

    issue(0); issue(1);

    for (int c = 0; c < NCHUNK; c++) {
        if (c < NCHUNK - 1) asm volatile("cp.async.wait_group 1;" ::: "memory");
        else                asm volatile("cp.async.wait_group 0;" ::: "memory");
        __syncthreads();

        const int s = c % NSTAGE;
        const __nv_bfloat16* AsH =
            (const __nv_bfloat16*)(smem + SM_A_OFF + s * A_STAGE_B) + warp_m * 64 * LDAB;
        const __nv_bfloat16* AsL = AsH + A_PLANE_B / 2;
        const __nv_bfloat16* BsH =
            (const __nv_bfloat16*)(smem + SM_B_OFF + s * B_STAGE_B) + warp_n * 64 * LDAB;
        const __nv_bfloat16* BsL = BsH + B_PLANE_B / 2;

#pragma unroll
        for (int k16 = 0; k16 < 2; k16++) {
            wmma::fragment<wmma::matrix_b, 16, 16, 16, __nv_bfloat16, wmma::col_major> bHf[4], bLf[4];
#pragma unroll
            for (int j = 0; j < 4; j++) {
                wmma::load_matrix_sync(bHf[j], BsH + j * 16 * LDAB + k16 * 16, LDAB);
                wmma::load_matrix_sync(bLf[j], BsL + j * 16 * LDAB + k16 * 16, LDAB);
            }
#pragma unroll
            for (int i = 0; i < 4; i++) {
                wmma::fragment<wmma::matrix_a, 16, 16, 16, __nv_bfloat16, wmma::row_major> aHf, aLf;
                wmma::load_matrix_sync(aHf, AsH + i * 16 * LDAB + k16 * 16, LDAB);
                wmma::load_matrix_sync(aLf, AsL + i * 16 * LDAB + k16 * 16, LDAB);
#pragma unroll
                for (int j = 0; j < 4; j++) {
                    wmma::mma_sync(acc[i][j], aHf, bHf[j], acc[i][j]);
                    wmma::mma_sync(acc[i][j], aLf, bHf[j], acc[i][j]);
                    wmma::mma_sync(acc[i][j], aHf, bLf[j], acc[i][j]);
                }
            }
        }
        __syncthreads();
        if (c + NSTAGE < NCHUNK) issue(c + NSTAGE);
    }

    // ---- epilogue: bias + tanh + bf16 hi/lo split + store ----
    float* scr = sScr + wid * (16 * 24);
    const int er = lane >> 1;
    const int ec = (lane & 1) * 8;
#pragma unroll
    for (int mi = 0; mi < 4; mi++) {
#pragma unroll
        for (int ni = 0; ni < 4; ni++) {
            wmma::store_matrix_sync(scr, acc[mi][ni], 24, wmma::mem_row_major);
            __syncwarp();
            int gr = m0 + warp_m * 64 + mi * 16 + er;
            int gc = n0 + warp_n * 64 + ni * 16 + ec;
            float4 v0 = *(float4*)(scr + er * 24 + ec);
            float4 v1 = *(float4*)(scr + er * 24 + ec + 4);
            const float* bb = bvec + gc;
            float vv[8] = { v0.x + bb[0], v0.y + bb[1], v0.z + bb[2], v0.w + bb[3],
                            v1.x + bb[4], v1.y + bb[5], v1.z + bb[6], v1.w + bb[7] };
            __align__(16) __nv_bfloat162 ph[4];
            __align__(16) __nv_bfloat162 pl[4];
#pragma unroll
            for (int e = 0; e < 4; e++) {
                __nv_bfloat16 h0, l0, h1, l1;
                split_bf16(tanhf(vv[2 * e]), h0, l0);
                split_bf16(tanhf(vv[2 * e + 1]), h1, l1);
                ph[e] = __halves2bfloat162(h0, h1);
                pl[e] = __halves2bfloat162(l0, l1);
            }
            size_t o = (size_t)gr * U_ + gc;
            *(uint4*)(nh + o) = *(uint4*)ph;
            *(uint4*)(nl + o) = *(uint4*)pl;
            __syncwarp();
        }
    }
}

// out[row] = h_last[row, :] @ Wo + bo
__global__ void final_proj_kernel(const float* __restrict__ Wo,
                                  const float* __restrict__ bo,
                                  float* __restrict__ out)
{
    const __nv_bfloat16* hh = g_h_hi[0];   // T_=80 even -> final state in buffer 0
    const __nv_bfloat16* hl = g_h_lo[0];
    int row = blockIdx.x;
    int tid = threadIdx.x;     // 128 threads
    float s = 0.0f;
    size_t base = (size_t)row * U_;
#pragma unroll 4
    for (int i = tid; i < U_; i += 128) {
        float hv = __bfloat162float(hh[base + i]) + __bfloat162float(hl[base + i]);
        s += hv * Wo[i];
    }
#pragma unroll
    for (int o = 16; o > 0; o >>= 1) s += __shfl_down_sync(0xffffffffu, s, o);
    __shared__ float red[4];
    if ((tid & 31) == 0) red[tid >> 5] = s;
    __syncthreads();
    if (tid == 0) out[row] = red[0] + red[1] + red[2] + red[3] + bo[0];
}

extern "C" void kernel_launch(void* const* d_in, const int* in_sizes, int n_in,
                              void* d_out, int out_size)
{
    const int*   inputs = (const int*)  d_in[0];
    const float* emb    = (const float*)d_in[1];
    const float* Wx     = (const float*)d_in[2];
    const float* Wh     = (const float*)d_in[3];
    const float* b      = (const float*)d_in[4];
    const float* Wo     = (const float*)d_in[5];
    const float* bo     = (const float*)d_in[6];
    float* out = (float*)d_out;

    cudaFuncSetAttribute(rnn_step_bf16, cudaFuncAttributeMaxDynamicSharedMemorySize,
                         SMEM_TOTAL);

    // Prep: split/transposed/padded bf16 weights + embedding, h0 = 0
    prep_bt_kernel<<<(U_ * KTOT + 255) / 256, 256>>>(Wh, Wx);
    prep_emb_kernel<<<(V_ * EPAD + 255) / 256, 256>>>(emb);
    {
        size_t n = (size_t)B_ * U_;
        zero_h_kernel<<<(int)((n + 255) / 256), 256>>>();
    }

    // 80 recurrence steps (ping-pong hi/lo planes)
    dim3 grid(U_ / NT, B_ / MT);
    for (int t = 0; t < T_; t++) {
        rnn_step_bf16<<<grid, NTHREADS, SMEM_TOTAL>>>(inputs, b, t);
    }

    final_proj_kernel<<<B_, 128>>>(Wo, bo, out);
}

// round 9
// speedup vs baseline: 2.1639x; 1.2956x over previous
#include <cuda_runtime.h>
#include <cuda_bf16.h>
#include <cstdint>
#include <cstddef>

#define B_ 4096
#define T_ 80
#define V_ 10000
#define E_ 100
#define U_ 1024

#define KTOT 1152            // 1024 (Wh) + 128 (Wx padded from 100)
#define EPAD 128             // padded embedding width
#define NCHUNK 36            // KTOT / 32
#define MT 128
#define NT 128
#define KC 32
#define NSTAGE 2
#define NTHREADS 128
#define LDAB 40              // row stride in bf16 elements (80 B): conflict-free ldmatrix

// byte sizes
#define ROWB (LDAB * 2)                  // 80 B per row
#define A_PLANE_B (MT * ROWB)            // 10240
#define A_STAGE_B (2 * A_PLANE_B)        // 20480 (hi + lo)
#define B_PLANE_B (NT * ROWB)            // 10240
#define B_STAGE_B (2 * B_PLANE_B)        // 20480
#define SM_A_OFF   0
#define SM_B_OFF   (NSTAGE * A_STAGE_B)                 // 40960
#define SM_IDX_OFF (SM_B_OFF + NSTAGE * B_STAGE_B)      // 81920
#define SMEM_TOTAL (SM_IDX_OFF + MT * 4)                // 82432

// ---- device scratch (allocation-free) ----
__device__ __align__(256) __nv_bfloat16 g_h_hi[2][(size_t)B_ * U_];
__device__ __align__(256) __nv_bfloat16 g_h_lo[2][(size_t)B_ * U_];
__device__ __align__(256) __nv_bfloat16 g_Bth[(size_t)U_ * KTOT];   // [n][k] hi
__device__ __align__(256) __nv_bfloat16 g_Btl[(size_t)U_ * KTOT];   // [n][k] lo
__device__ __align__(256) __nv_bfloat16 g_emb_hi[(size_t)V_ * EPAD];
__device__ __align__(256) __nv_bfloat16 g_emb_lo[(size_t)V_ * EPAD];

static __device__ __forceinline__ uint32_t smem_u32(const void* p) {
    uint32_t a;
    asm("{ .reg .u64 t; cvta.to.shared.u64 t, %1; cvt.u32.u64 %0, t; }" : "=r"(a) : "l"(p));
    return a;
}
static __device__ __forceinline__ void cp_async16(uint32_t s, const void* g) {
    asm volatile("cp.async.cg.shared.global [%0], [%1], 16;" :: "r"(s), "l"(g));
}
static __device__ __forceinline__ void split_bf16(float v, __nv_bfloat16& hi, __nv_bfloat16& lo) {
    hi = __float2bfloat16(v);
    lo = __float2bfloat16(v - __bfloat162float(hi));
}
static __device__ __forceinline__ void ldsm4(uint32_t* r, uint32_t addr) {
    asm volatile("ldmatrix.sync.aligned.m8n8.x4.shared.b16 {%0,%1,%2,%3}, [%4];"
                 : "=r"(r[0]), "=r"(r[1]), "=r"(r[2]), "=r"(r[3]) : "r"(addr));
}
static __device__ __forceinline__ void mma_bf16(float* c, const uint32_t* a,
                                                uint32_t b0, uint32_t b1) {
    asm volatile("mma.sync.aligned.m16n8k16.row.col.f32.bf16.bf16.f32 "
                 "{%0,%1,%2,%3}, {%4,%5,%6,%7}, {%8,%9}, {%0,%1,%2,%3};"
                 : "+f"(c[0]), "+f"(c[1]), "+f"(c[2]), "+f"(c[3])
                 : "r"(a[0]), "r"(a[1]), "r"(a[2]), "r"(a[3]), "r"(b0), "r"(b1));
}

// ---------------- prep kernels ----------------
__global__ void prep_bt_kernel(const float* __restrict__ Wh, const float* __restrict__ Wx) {
    int idx = blockIdx.x * 256 + threadIdx.x;
    if (idx >= U_ * KTOT) return;
    int n = idx / KTOT;
    int k = idx - n * KTOT;
    float v = 0.0f;
    if (k < U_)            v = Wh[(size_t)k * U_ + n];
    else if (k < U_ + E_)  v = Wx[(size_t)(k - U_) * U_ + n];
    __nv_bfloat16 hi, lo; split_bf16(v, hi, lo);
    g_Bth[idx] = hi; g_Btl[idx] = lo;
}
__global__ void prep_emb_kernel(const float* __restrict__ emb) {
    int idx = blockIdx.x * 256 + threadIdx.x;
    if (idx >= V_ * EPAD) return;
    int tok = idx >> 7;
    int k = idx & (EPAD - 1);
    float v = (k < E_) ? emb[(size_t)tok * E_ + k] : 0.0f;
    __nv_bfloat16 hi, lo; split_bf16(v, hi, lo);
    g_emb_hi[idx] = hi; g_emb_lo[idx] = lo;
}
__global__ void zero_h_kernel() {
    size_t i = (size_t)blockIdx.x * blockDim.x + threadIdx.x;
    if (i < (size_t)B_ * U_) {
        g_h_hi[0][i] = __float2bfloat16(0.0f);
        g_h_lo[0][i] = __float2bfloat16(0.0f);
    }
}

// ---------------- recurrence step: raw mma.m16n8k16 bf16, 3-MMA split ----------------
// Grid: (U_/NT = 8, B_/MT = 32) = 256 CTAs, 128 threads (4 warps, 2x2 -> 64x64 tiles).
// 2 CTAs resident per SM.
__global__ __launch_bounds__(NTHREADS, 2)
void rnn_step_bf16(const int* __restrict__ inputs, const float* __restrict__ bvec, int t)
{
    extern __shared__ char smem[];
    int* sIdx = (int*)(smem + SM_IDX_OFF);
    const uint32_t sbase = smem_u32(smem);

    const int tid = threadIdx.x;
    const int wid = tid >> 5;
    const int lane = tid & 31;
    const int warp_m = wid & 1;       // 2 m-tiles of 64
    const int warp_n = wid >> 1;      // 2 n-tiles of 64
    const int n0 = blockIdx.x * NT;
    const int m0 = blockIdx.y * MT;

    const __nv_bfloat16* __restrict__ hh = g_h_hi[t & 1];
    const __nv_bfloat16* __restrict__ hl = g_h_lo[t & 1];
    __nv_bfloat16* __restrict__ nh = g_h_hi[(t & 1) ^ 1];
    __nv_bfloat16* __restrict__ nl = g_h_lo[(t & 1) ^ 1];

    sIdx[tid] = inputs[(size_t)(m0 + tid) * T_ + t];
    __syncthreads();

    float acc[4][8][4];
#pragma unroll
    for (int i = 0; i < 4; i++)
#pragma unroll
        for (int j = 0; j < 8; j++)
#pragma unroll
            for (int e = 0; e < 4; e++) acc[i][j][e] = 0.0f;

    // ldmatrix lane address components
    const int a_r = lane & 15;                      // A row within 16
    const int a_c = (lane >> 4) * 16;               // A byte offset (k half)
    const int b_r = (lane & 7) + ((lane >> 4) << 3);// B n-row within 16
    const int b_c = ((lane >> 3) & 1) * 16;         // B byte offset (k half)

    auto issue = [&](int c) {
        const int s = c % NSTAGE;
        const uint32_t aHiB = sbase + SM_A_OFF + (uint32_t)(s * A_STAGE_B);
        const uint32_t aLoB = aHiB + A_PLANE_B;
        if (c < 32) {
            const __nv_bfloat16* sh = hh + (size_t)m0 * U_ + c * KC;
            const __nv_bfloat16* sl = hl + (size_t)m0 * U_ + c * KC;
#pragma unroll
            for (int r = 0; r < 4; r++) {
                int idx = r * NTHREADS + tid;
                int row = idx >> 2, sc = idx & 3;
                uint32_t off = (uint32_t)(row * ROWB + sc * 16);
                cp_async16(aHiB + off, sh + (size_t)row * U_ + sc * 8);
                cp_async16(aLoB + off, sl + (size_t)row * U_ + sc * 8);
            }
        } else {
            const int kb = (c - 32) * KC;
#pragma unroll
            for (int r = 0; r < 4; r++) {
                int idx = r * NTHREADS + tid;
                int row = idx >> 2, sc = idx & 3;
                uint32_t off = (uint32_t)(row * ROWB + sc * 16);
                size_t g = (size_t)sIdx[row] * EPAD + kb + sc * 8;
                cp_async16(aHiB + off, g_emb_hi + g);
                cp_async16(aLoB + off, g_emb_lo + g);
            }
        }
        const uint32_t bHiB = sbase + SM_B_OFF + (uint32_t)(s * B_STAGE_B);
        const uint32_t bLoB = bHiB + B_PLANE_B;
        const __nv_bfloat16* bh = g_Bth + (size_t)n0 * KTOT + c * KC;
        const __nv_bfloat16* bl = g_Btl + (size_t)n0 * KTOT + c * KC;
#pragma unroll
        for (int r = 0; r < 4; r++) {
            int idx = r * NTHREADS + tid;
            int row = idx >> 2, sc = idx & 3;
            uint32_t off = (uint32_t)(row * ROWB + sc * 16);
            cp_async16(bHiB + off, bh + (size_t)row * KTOT + sc * 8);
            cp_async16(bLoB + off, bl + (size_t)row * KTOT + sc * 8);
        }
        asm volatile("cp.async.commit_group;" ::: "memory");
    };

    issue(0); issue(1);

    for (int c = 0; c < NCHUNK; c++) {
        if (c < NCHUNK - 1) asm volatile("cp.async.wait_group 1;" ::: "memory");
        else                asm volatile("cp.async.wait_group 0;" ::: "memory");
        __syncthreads();

        const int s = c % NSTAGE;
        const uint32_t aBase = sbase + SM_A_OFF + (uint32_t)(s * A_STAGE_B)
                             + (uint32_t)(warp_m * 64 * ROWB);
        const uint32_t bBase = sbase + SM_B_OFF + (uint32_t)(s * B_STAGE_B)
                             + (uint32_t)(warp_n * 64 * ROWB);

#pragma unroll
        for (int k16 = 0; k16 < 2; k16++) {
            uint32_t ah[4][4], al[4][4];
#pragma unroll
            for (int i = 0; i < 4; i++) {
                uint32_t addr = aBase + (uint32_t)((i * 16 + a_r) * ROWB + k16 * 32 + a_c);
                ldsm4(ah[i], addr);
                ldsm4(al[i], addr + A_PLANE_B);
            }
#pragma unroll
            for (int jj = 0; jj < 4; jj++) {
                uint32_t bh[4], bl[4];
                uint32_t baddr = bBase + (uint32_t)((jj * 16 + b_r) * ROWB + k16 * 32 + b_c);
                ldsm4(bh, baddr);
                ldsm4(bl, baddr + B_PLANE_B);
#pragma unroll
                for (int i = 0; i < 4; i++) {
                    mma_bf16(acc[i][2 * jj],     ah[i], bh[0], bh[1]);
                    mma_bf16(acc[i][2 * jj],     al[i], bh[0], bh[1]);
                    mma_bf16(acc[i][2 * jj],     ah[i], bl[0], bl[1]);
                    mma_bf16(acc[i][2 * jj + 1], ah[i], bh[2], bh[3]);
                    mma_bf16(acc[i][2 * jj + 1], al[i], bh[2], bh[3]);
                    mma_bf16(acc[i][2 * jj + 1], ah[i], bl[2], bl[3]);
                }
            }
        }
        __syncthreads();
        if (c + NSTAGE < NCHUNK) issue(c + NSTAGE);
    }

    // ---- epilogue: bias + tanh + bf16 hi/lo split + direct store from acc frags ----
    // c0,c1 -> (row = lane>>2, col = (lane&3)*2 {,+1}); c2,c3 -> row+8.
    const int er = lane >> 2;
    const int ec = (lane & 3) * 2;
#pragma unroll
    for (int j = 0; j < 8; j++) {
        int gc = n0 + warp_n * 64 + j * 8 + ec;
        float bia0 = bvec[gc], bia1 = bvec[gc + 1];
#pragma unroll
        for (int i = 0; i < 4; i++) {
            int gr = m0 + warp_m * 64 + i * 16 + er;
            float t0 = tanhf(acc[i][j][0] + bia0);
            float t1 = tanhf(acc[i][j][1] + bia1);
            float t2 = tanhf(acc[i][j][2] + bia0);
            float t3 = tanhf(acc[i][j][3] + bia1);
            __nv_bfloat16 h0, l0, h1, l1;
            split_bf16(t0, h0, l0); split_bf16(t1, h1, l1);
            size_t o0 = (size_t)gr * U_ + gc;
            *(__nv_bfloat162*)(nh + o0) = __halves2bfloat162(h0, h1);
            *(__nv_bfloat162*)(nl + o0) = __halves2bfloat162(l0, l1);
            split_bf16(t2, h0, l0); split_bf16(t3, h1, l1);
            size_t o1 = (size_t)(gr + 8) * U_ + gc;
            *(__nv_bfloat162*)(nh + o1) = __halves2bfloat162(h0, h1);
            *(__nv_bfloat162*)(nl + o1) = __halves2bfloat162(l0, l1);
        }
    }
}

// out[row] = h_last[row, :] @ Wo + bo
__global__ void final_proj_kernel(const float* __restrict__ Wo,
                                  const float* __restrict__ bo,
                                  float* __restrict__ out)
{
    const __nv_bfloat16* hh = g_h_hi[0];   // T_=80 even -> final state in buffer 0
    const __nv_bfloat16* hl = g_h_lo[0];
    int row = blockIdx.x;
    int tid = threadIdx.x;     // 128 threads
    float s = 0.0f;
    size_t base = (size_t)row * U_;
#pragma unroll 4
    for (int i = tid; i < U_; i += 128) {
        float hv = __bfloat162float(hh[base + i]) + __bfloat162float(hl[base + i]);
        s += hv * Wo[i];
    }
#pragma unroll
    for (int o = 16; o > 0; o >>= 1) s += __shfl_down_sync(0xffffffffu, s, o);
    __shared__ float red[4];
    if ((tid & 31) == 0) red[tid >> 5] = s;
    __syncthreads();
    if (tid == 0) out[row] = red[0] + red[1] + red[2] + red[3] + bo[0];
}

extern "C" void kernel_launch(void* const* d_in, const int* in_sizes, int n_in,
                              void* d_out, int out_size)
{
    const int*   inputs = (const int*)  d_in[0];
    const float* emb    = (const float*)d_in[1];
    const float* Wx     = (const float*)d_in[2];
    const float* Wh     = (const float*)d_in[3];
    const float* b      = (const float*)d_in[4];
    const float* Wo     = (const float*)d_in[5];
    const float* bo     = (const float*)d_in[6];
    float* out = (float*)d_out;

    cudaFuncSetAttribute(rnn_step_bf16, cudaFuncAttributeMaxDynamicSharedMemorySize,
                         SMEM_TOTAL);

    // Prep: split/transposed/padded bf16 weights + embedding, h0 = 0
    prep_bt_kernel<<<(U_ * KTOT + 255) / 256, 256>>>(Wh, Wx);
    prep_emb_kernel<<<(V_ * EPAD + 255) / 256, 256>>>(emb);
    {
        size_t n = (size_t)B_ * U_;
        zero_h_kernel<<<(int)((n + 255) / 256), 256>>>();
    }

    // 80 recurrence steps (ping-pong hi/lo planes)
    dim3 grid(U_ / NT, B_ / MT);
    for (int t = 0; t < T_; t++) {
        rnn_step_bf16<<<grid, NTHREADS, SMEM_TOTAL>>>(inputs, b, t);
    }

    final_proj_kernel<<<B_, 128>>>(Wo, bo, out);
}